// round 1
// baseline (speedup 1.0000x reference)
#include <cuda_runtime.h>

// ---------------------------------------------------------------------------
// PolicyNetwork: two masked-softmax MLP heads.
//  op branch:   N=102400 rows, MLP(768->32->16->1), softmax over ALL rows
//  prlvl branch: 1024x64 rows, MLP(513->32->16->1), softmax per dag over 64
// Algebraic split: layer-1 contributions of y[dag] and z are precomputed per
// dag, so the hot GEMM is only [N x 256] x [256 x 32].
// ---------------------------------------------------------------------------

#define NOPS  102400
#define NDAG  1024
#define OPD   100
#define EDIM  256
#define H1D   32
#define H2D   16
#define NWRK  64
#define TILE  256
#define NBLK  (NOPS / TILE)   // 400

// Scratch (no allocations allowed)
__device__ float g_Aop[NDAG * H1D];   // per-dag layer1 bias for op branch (incl b1)
__device__ float g_Apr[NDAG * H1D];   // per-dag layer1 bias for prlvl branch (incl b1)
__device__ float g_bmax[NBLK];
__device__ float g_bsum[NBLK];
__device__ float g_stat[2];           // [0]=global max, [1]=1/sum

// ---------------------------------------------------------------------------
// Precompute per-dag layer-1 partials:
//   g_Aop[d][j] = op_b1[j] + sum_k y[d][k]*opW1[256+k][j] + sum_k z[k]*opW1[512+k][j]
//   g_Apr[d][j] = pr_b1[j] + sum_k y[d][k]*prW1[1+k][j]   + sum_k z[k]*prW1[257+k][j]
// one warp per dag, lane = output column j
// ---------------------------------------------------------------------------
__global__ __launch_bounds__(128) void precompute_kernel(
    const float* __restrict__ y, const float* __restrict__ z,
    const float* __restrict__ opW1, const float* __restrict__ opb1,
    const float* __restrict__ prW1, const float* __restrict__ prb1)
{
    int warp = threadIdx.x >> 5;
    int lane = threadIdx.x & 31;
    int d = blockIdx.x * 4 + warp;
    if (d >= NDAG) return;
    const float* yd = y + d * EDIM;
    float aop = opb1[lane];
    float apr = prb1[lane];
    #pragma unroll 4
    for (int k = 0; k < EDIM; k++) {
        float yv = __ldg(yd + k);
        float zv = __ldg(z + k);
        aop = fmaf(yv, __ldg(opW1 + (EDIM + k) * H1D + lane), aop);
        aop = fmaf(zv, __ldg(opW1 + (2 * EDIM + k) * H1D + lane), aop);
        apr = fmaf(yv, __ldg(prW1 + (1 + k) * H1D + lane), apr);
        apr = fmaf(zv, __ldg(prW1 + (1 + EDIM + k) * H1D + lane), apr);
    }
    g_Aop[d * H1D + lane] = aop;
    g_Apr[d * H1D + lane] = apr;
}

// ---------------------------------------------------------------------------
// Main op kernel: tile of 256 ops per block.
// Layer1 GEMM [256x256]x[256x32] with per-thread 8-ops x 4-cols register tile,
// then fused add/relu/layer2/layer3/mask + per-block online softmax partials.
// Dynamic smem layout (floats):
//   [0,8192)        W1 x-part  (256 rows x 32 cols)
//   [8192,16640)    x tile, stride 33   (reused as h1, stride 33)
//   [16640,17152)   W2 (32x16)
//   [17152,17168)   b2
//   [17168,17184)   W3
//   [17184,17200)   reduce scratch
// ---------------------------------------------------------------------------
#define SMEM_FLOATS 17200
#define SMEM_BYTES  (SMEM_FLOATS * 4)

__global__ __launch_bounds__(256) void op_main_kernel(
    const float* __restrict__ x,
    const float* __restrict__ opW1,
    const float* __restrict__ opW2, const float* __restrict__ opb2,
    const float* __restrict__ opW3, const float* __restrict__ opb3,
    const float* __restrict__ opmsk,
    float* __restrict__ out)
{
    extern __shared__ float sm[];
    float* s_w1  = sm;              // 8192
    float* s_x   = sm + 8192;       // 256*33 = 8448
    float* s_w2  = sm + 16640;      // 512
    float* s_b2  = s_w2 + 512;      // 16
    float* s_w3  = s_b2 + 16;       // 16
    float* s_red = s_w3 + 16;       // 16

    const int tid = threadIdx.x;

    for (int i = tid; i < 8192; i += 256) s_w1[i] = opW1[i];
    for (int i = tid; i < 512; i += 256) s_w2[i] = opW2[i];
    if (tid < 16) { s_b2[tid] = opb2[tid]; s_w3[tid] = opW3[tid]; }

    const int tile = blockIdx.x * TILE;
    const int cg = tid & 7;    // column group: cols cg*4 .. cg*4+3
    const int og = tid >> 3;   // op group: ops og*8 .. og*8+7

    float acc[8][4];
    #pragma unroll
    for (int o = 0; o < 8; o++)
        #pragma unroll
        for (int c = 0; c < 4; c++) acc[o][c] = 0.f;

    for (int kc = 0; kc < EDIM; kc += 32) {
        __syncthreads();
        // stage x chunk: [256 ops][32 k], stride 33 (conflict-free)
        #pragma unroll 4
        for (int it = 0; it < 32; it++) {
            int idx = it * 256 + tid;          // 0..8191
            int op = idx >> 5, k = idx & 31;
            s_x[op * 33 + k] = x[(tile + op) * EDIM + kc + k];
        }
        __syncthreads();
        #pragma unroll
        for (int kk = 0; kk < 32; kk++) {
            const float4 w = ((const float4*)s_w1)[(kc + kk) * 8 + cg];
            #pragma unroll
            for (int o = 0; o < 8; o++) {
                float xv = s_x[(og * 8 + o) * 33 + kk];
                acc[o][0] = fmaf(xv, w.x, acc[o][0]);
                acc[o][1] = fmaf(xv, w.y, acc[o][1]);
                acc[o][2] = fmaf(xv, w.z, acc[o][2]);
                acc[o][3] = fmaf(xv, w.w, acc[o][3]);
            }
        }
    }
    __syncthreads();

    // add per-dag partial + bias, relu, exchange h1 through shared (stride 33)
    #pragma unroll
    for (int o = 0; o < 8; o++) {
        int op = og * 8 + o;
        int dag = (tile + op) / OPD;
        #pragma unroll
        for (int c = 0; c < 4; c++) {
            float v = acc[o][c] + g_Aop[dag * H1D + cg * 4 + c];
            s_x[op * 33 + cg * 4 + c] = fmaxf(v, 0.f);
        }
    }
    __syncthreads();

    // layers 2/3 + mask: one op per thread
    const int op = tid;
    const int gop = tile + op;
    float h2[H2D];
    #pragma unroll
    for (int j = 0; j < H2D; j++) h2[j] = s_b2[j];
    #pragma unroll
    for (int k = 0; k < H1D; k++) {
        float hv = s_x[op * 33 + k];
        #pragma unroll
        for (int j = 0; j < H2D; j++) h2[j] = fmaf(hv, s_w2[k * H2D + j], h2[j]);
    }
    float l = opb3[0];
    #pragma unroll
    for (int j = 0; j < H2D; j++) l = fmaf(fmaxf(h2[j], 0.f), s_w3[j], l);
    l -= (1.f - opmsk[gop]) * 1000.f;
    out[gop] = l;

    // per-block online softmax partials
    float m = l;
    #pragma unroll
    for (int off = 16; off; off >>= 1)
        m = fmaxf(m, __shfl_xor_sync(0xffffffffu, m, off));
    int wid = tid >> 5, lane = tid & 31;
    if (lane == 0) s_red[wid] = m;
    __syncthreads();
    float bm = s_red[0];
    #pragma unroll
    for (int i = 1; i < 8; i++) bm = fmaxf(bm, s_red[i]);
    float e = __expf(l - bm);
    #pragma unroll
    for (int off = 16; off; off >>= 1)
        e += __shfl_xor_sync(0xffffffffu, e, off);
    if (lane == 0) s_red[8 + wid] = e;
    __syncthreads();
    if (tid == 0) {
        float s = 0.f;
        #pragma unroll
        for (int i = 0; i < 8; i++) s += s_red[8 + i];
        g_bmax[blockIdx.x] = bm;
        g_bsum[blockIdx.x] = s;
    }
}

// ---------------------------------------------------------------------------
// Merge the 400 block partials into global (max, 1/sum)
// ---------------------------------------------------------------------------
__global__ __launch_bounds__(256) void softmax_reduce_kernel()
{
    __shared__ float sr[16];
    __shared__ float sM;
    const int tid = threadIdx.x;
    float m = -1e30f;
    for (int i = tid; i < NBLK; i += 256) m = fmaxf(m, g_bmax[i]);
    #pragma unroll
    for (int off = 16; off; off >>= 1)
        m = fmaxf(m, __shfl_xor_sync(0xffffffffu, m, off));
    int wid = tid >> 5, lane = tid & 31;
    if (lane == 0) sr[wid] = m;
    __syncthreads();
    if (tid == 0) {
        float M = sr[0];
        #pragma unroll
        for (int i = 1; i < 8; i++) M = fmaxf(M, sr[i]);
        sM = M;
    }
    __syncthreads();
    const float M = sM;
    float s = 0.f;
    for (int i = tid; i < NBLK; i += 256)
        s += g_bsum[i] * __expf(g_bmax[i] - M);
    #pragma unroll
    for (int off = 16; off; off >>= 1)
        s += __shfl_xor_sync(0xffffffffu, s, off);
    if (lane == 0) sr[8 + wid] = s;
    __syncthreads();
    if (tid == 0) {
        float S = 0.f;
        #pragma unroll
        for (int i = 0; i < 8; i++) S += sr[8 + i];
        g_stat[0] = M;
        g_stat[1] = 1.f / S;
    }
}

__global__ __launch_bounds__(256) void op_finalize_kernel(float* __restrict__ out)
{
    int i = blockIdx.x * 256 + threadIdx.x;
    float M = g_stat[0], inv = g_stat[1];
    if (i < NOPS) out[i] = __expf(out[i] - M) * inv;
}

// ---------------------------------------------------------------------------
// prlvl branch: one block (64 threads) per dag; thread = worker
// ---------------------------------------------------------------------------
__global__ __launch_bounds__(64) void prlvl_kernel(
    const float* __restrict__ prW1,
    const float* __restrict__ prW2, const float* __restrict__ prb2,
    const float* __restrict__ prW3, const float* __restrict__ prb3,
    const float* __restrict__ prmsk,
    float* __restrict__ out)
{
    __shared__ float sA[H1D], sr0[H1D], sw2[H1D * H2D], sb2[H2D], sw3[H2D], sl[NWRK];
    const int d = blockIdx.x;
    const int w = threadIdx.x;
    if (w < H1D) { sA[w] = g_Apr[d * H1D + w]; sr0[w] = prW1[w]; }  // prW1 row 0 = limit weights
    for (int i = w; i < H1D * H2D; i += NWRK) sw2[i] = prW2[i];
    if (w < H2D) { sb2[w] = prb2[w]; sw3[w] = prW3[w]; }
    __syncthreads();

    const float limit = (float)(w + 1);
    float h2[H2D];
    #pragma unroll
    for (int j = 0; j < H2D; j++) h2[j] = sb2[j];
    #pragma unroll
    for (int k = 0; k < H1D; k++) {
        float hv = fmaxf(fmaf(limit, sr0[k], sA[k]), 0.f);
        #pragma unroll
        for (int j = 0; j < H2D; j++) h2[j] = fmaf(hv, sw2[k * H2D + j], h2[j]);
    }
    float l = prb3[0];
    #pragma unroll
    for (int j = 0; j < H2D; j++) l = fmaf(fmaxf(h2[j], 0.f), sw3[j], l);
    l -= (1.f - prmsk[d * NWRK + w]) * 1000.f;
    sl[w] = l;
    __syncthreads();
    float m = -1e30f;
    #pragma unroll 8
    for (int i = 0; i < NWRK; i++) m = fmaxf(m, sl[i]);
    float s = 0.f;
    #pragma unroll 8
    for (int i = 0; i < NWRK; i++) s += __expf(sl[i] - m);
    out[NOPS + d * NWRK + w] = __expf(l - m) / s;
}

// ---------------------------------------------------------------------------
// Launch
// ---------------------------------------------------------------------------
extern "C" void kernel_launch(void* const* d_in, const int* in_sizes, int n_in,
                              void* d_out, int out_size)
{
    // inputs (metadata order): [num_ops, (num_dags, num_workers,)] x, y, z,
    // op_msk, prlvl_msk, op_W1,b1,W2,b2,W3,b3, pr_W1,b1,W2,b2,W3,b3
    const int xi = n_in - 17;  // index of x regardless of whether scalars are present
    const float* x     = (const float*)d_in[xi + 0];
    const float* y     = (const float*)d_in[xi + 1];
    const float* z     = (const float*)d_in[xi + 2];
    const float* opmsk = (const float*)d_in[xi + 3];
    const float* prmsk = (const float*)d_in[xi + 4];
    const float* opW1  = (const float*)d_in[xi + 5];
    const float* opb1  = (const float*)d_in[xi + 6];
    const float* opW2  = (const float*)d_in[xi + 7];
    const float* opb2  = (const float*)d_in[xi + 8];
    const float* opW3  = (const float*)d_in[xi + 9];
    const float* opb3  = (const float*)d_in[xi + 10];
    const float* prW1  = (const float*)d_in[xi + 11];
    const float* prb1  = (const float*)d_in[xi + 12];
    const float* prW2  = (const float*)d_in[xi + 13];
    const float* prb2  = (const float*)d_in[xi + 14];
    const float* prW3  = (const float*)d_in[xi + 15];
    const float* prb3  = (const float*)d_in[xi + 16];
    float* out = (float*)d_out;

    cudaFuncSetAttribute(op_main_kernel,
                         cudaFuncAttributeMaxDynamicSharedMemorySize, SMEM_BYTES);

    precompute_kernel<<<NDAG / 4, 128>>>(y, z, opW1, opb1, prW1, prb1);
    op_main_kernel<<<NBLK, 256, SMEM_BYTES>>>(x, opW1, opW2, opb2, opW3, opb3,
                                              opmsk, out);
    softmax_reduce_kernel<<<1, 256>>>();
    op_finalize_kernel<<<NBLK, 256>>>(out);
    prlvl_kernel<<<NDAG, 64>>>(prW1, prW2, prb2, prW3, prb3, prmsk, out);
}

// round 2
// speedup vs baseline: 1.1928x; 1.1928x over previous
#include <cuda_runtime.h>
#include <cstdint>

#define NOPS  102400
#define NDAG  1024
#define OPD   100
#define EDIM  256
#define H1D   32
#define H2D   16
#define NWRK  64
#define TILE  256
#define NBLK  (NOPS / TILE)   // 400

typedef unsigned long long ull;

// Scratch (no allocations allowed)
__device__ float g_Aop[NDAG * H1D];
__device__ float g_Apr[NDAG * H1D];
__device__ float g_bmax[NBLK];
__device__ float g_bsum[NBLK];

// ---------------- f32x2 helpers ----------------
__device__ __forceinline__ ull pack2(float a, float b) {
    ull r; asm("mov.b64 %0,{%1,%2};" : "=l"(r) : "f"(a), "f"(b)); return r;
}
__device__ __forceinline__ void unpack2(ull v, float& a, float& b) {
    asm("mov.b64 {%0,%1},%2;" : "=f"(a), "=f"(b) : "l"(v));
}
__device__ __forceinline__ void fma2(ull& d, ull a, ull b) {
    asm("fma.rn.f32x2 %0,%1,%2,%0;" : "+l"(d) : "l"(a), "l"(b));
}
__device__ __forceinline__ void cp16(uint32_t dst, const void* src) {
    asm volatile("cp.async.cg.shared.global [%0], [%1], 16;" :: "r"(dst), "l"(src));
}

// ---------------------------------------------------------------------------
// Precompute per-dag layer-1 partials (y and z contributions + b1)
// ---------------------------------------------------------------------------
__global__ __launch_bounds__(128) void precompute_kernel(
    const float* __restrict__ y, const float* __restrict__ z,
    const float* __restrict__ opW1, const float* __restrict__ opb1,
    const float* __restrict__ prW1, const float* __restrict__ prb1)
{
    int warp = threadIdx.x >> 5;
    int lane = threadIdx.x & 31;
    int d = blockIdx.x * 4 + warp;
    if (d >= NDAG) return;
    const float* yd = y + d * EDIM;
    float aop = opb1[lane];
    float apr = prb1[lane];
    #pragma unroll 4
    for (int k = 0; k < EDIM; k++) {
        float yv = __ldg(yd + k);
        float zv = __ldg(z + k);
        aop = fmaf(yv, __ldg(opW1 + (EDIM + k) * H1D + lane), aop);
        aop = fmaf(zv, __ldg(opW1 + (2 * EDIM + k) * H1D + lane), aop);
        apr = fmaf(yv, __ldg(prW1 + (1 + k) * H1D + lane), apr);
        apr = fmaf(zv, __ldg(prW1 + (1 + EDIM + k) * H1D + lane), apr);
    }
    g_Aop[d * H1D + lane] = aop;
    g_Apr[d * H1D + lane] = apr;
}

// ---------------------------------------------------------------------------
// Main op kernel.
// 256 threads, tile of 256 ops. Per-thread: 4 ops x 8 cols, k-paired f32x2.
// x staged via cp.async double-buffer, XOR-swizzled, stride 36 (16B aligned).
// smem layout (floats):
//   [0,8192)        W1 x-part, k-pair packed + col-permuted
//   [8192,26624)    x double buffer: 2 x (256 ops x 36)
//   [26624,27136)   W2 (32x16)
//   [27136,27152)   b2
//   [27152,27168)   W3
//   [27168,27184)   reduce scratch
// ---------------------------------------------------------------------------
#define XSTR 36
#define XBUF (TILE * XSTR)          // 9216
#define SM_X   8192
#define SM_W2  (SM_X + 2 * XBUF)    // 26624
#define SM_B2  (SM_W2 + 512)
#define SM_W3  (SM_B2 + 16)
#define SM_RED (SM_W3 + 16)
#define SM_FLOATS (SM_RED + 16)     // 27184
#define SMEM_BYTES (SM_FLOATS * 4)  // 108736

__global__ __launch_bounds__(256, 2) void op_main_kernel(
    const float* __restrict__ x,
    const float* __restrict__ opW1,
    const float* __restrict__ opW2, const float* __restrict__ opb2,
    const float* __restrict__ opW3, const float* __restrict__ opb3,
    const float* __restrict__ opmsk,
    float* __restrict__ out)
{
    extern __shared__ float sm[];
    float* s_w1p = sm;
    float* s_xb  = sm + SM_X;
    float* s_w2  = sm + SM_W2;
    float* s_b2  = sm + SM_B2;
    float* s_w3  = sm + SM_W3;
    float* s_red = sm + SM_RED;

    const int tid  = threadIdx.x;
    const int tile = blockIdx.x * TILE;
    const int cg   = tid & 3;    // col group: cols cg*8 .. cg*8+7
    const int og   = tid >> 2;   // op group:  ops  og*4 .. og*4+3
    const int swz  = og & 6;

    // --- stage chunk c (32 k-values) of x into buffer buf via cp.async ---
    auto stage = [&](int c, int buf) {
        const float* src = x + (size_t)tile * EDIM + c * 32;
        float* dstb = s_xb + buf * XBUF;
        #pragma unroll
        for (int i = 0; i < 8; i++) {
            int lin = i * 256 + tid;
            int op = lin >> 3, q = lin & 7;          // q: float4 index (k-pairs 2q,2q+1)
            int s2 = (op >> 2) & 6;
            uint32_t dst = (uint32_t)__cvta_generic_to_shared(
                dstb + op * XSTR + 2 * ((2 * q) ^ s2));
            cp16(dst, src + op * EDIM + q * 4);
        }
        asm volatile("cp.async.commit_group;");
    };

    stage(0, 0);

    // pack W1 x-part: element (k,col) -> [(k>>1)*64 + ((col&7)*4 + (col>>3))*2 + (k&1)]
    for (int i = tid; i < 8192; i += 256) {
        int k = i >> 5, col = i & 31;
        s_w1p[(k >> 1) * 64 + ((col & 7) * 4 + (col >> 3)) * 2 + (k & 1)] = opW1[i];
    }
    for (int i = tid; i < 512; i += 256) s_w2[i] = opW2[i];
    if (tid < 16) { s_b2[tid] = opb2[tid]; s_w3[tid] = opW3[tid]; }

    stage(1, 1);

    ull acc[4][8];
    #pragma unroll
    for (int o = 0; o < 4; o++)
        #pragma unroll
        for (int j = 0; j < 8; j++) acc[o][j] = 0ull;

    int base0 = (og * 4 + 0) * XSTR;
    int base1 = (og * 4 + 1) * XSTR;
    int base2 = (og * 4 + 2) * XSTR;
    int base3 = (og * 4 + 3) * XSTR;

    for (int c = 0; c < 8; c++) {
        if (c < 7) {
            if (c + 1 < 8 && c >= 1) stage(c + 1, (c + 1) & 1);  // chunks 0,1 pre-staged
            asm volatile("cp.async.wait_group 1;");
        } else {
            asm volatile("cp.async.wait_group 0;");
        }
        __syncthreads();

        const float* xb = s_xb + (c & 1) * XBUF;
        const int K2b = c * 16;
        #pragma unroll
        for (int kk2 = 0; kk2 < 16; kk2++) {
            int xoff = 2 * (kk2 ^ swz);
            ull xv0 = *(const ull*)(xb + base0 + xoff);
            ull xv1 = *(const ull*)(xb + base1 + xoff);
            ull xv2 = *(const ull*)(xb + base2 + xoff);
            ull xv3 = *(const ull*)(xb + base3 + xoff);
            const float* wrow = s_w1p + (K2b + kk2) * 64 + cg * 2;
            #pragma unroll
            for (int j = 0; j < 8; j++) {
                ull wv = *(const ull*)(wrow + j * 8);
                fma2(acc[0][j], xv0, wv);
                fma2(acc[1][j], xv1, wv);
                fma2(acc[2][j], xv2, wv);
                fma2(acc[3][j], xv3, wv);
            }
        }
        __syncthreads();
    }

    // --- fold k-halves, add per-dag partial, relu, exchange through shared ---
    float* s_h = s_xb;   // reuse buffer 0 (256 x 36)
    #pragma unroll
    for (int o = 0; o < 4; o++) {
        int op = og * 4 + o;
        int dag = (tile + op) / OPD;
        const float* A = g_Aop + dag * H1D;
        #pragma unroll
        for (int j = 0; j < 8; j++) {
            float a, b; unpack2(acc[o][j], a, b);
            int col = cg * 8 + j;
            s_h[op * XSTR + col] = fmaxf(a + b + A[col], 0.f);
        }
    }
    __syncthreads();

    // --- layers 2/3 + mask: one op per thread, j-paired f32x2 ---
    const int gop = tile + tid;
    ull h2[8];
    {
        const ull* b2p = (const ull*)s_b2;
        #pragma unroll
        for (int jp = 0; jp < 8; jp++) h2[jp] = b2p[jp];
    }
    const float* hrow = s_h + tid * XSTR;
    #pragma unroll
    for (int kp = 0; kp < 16; kp++) {
        float2 hv = *(const float2*)(hrow + 2 * kp);
        ull ha = pack2(hv.x, hv.x);
        ull hb = pack2(hv.y, hv.y);
        const ulonglong2* w2a = (const ulonglong2*)(s_w2 + (2 * kp) * 16);
        const ulonglong2* w2b = (const ulonglong2*)(s_w2 + (2 * kp + 1) * 16);
        #pragma unroll
        for (int q = 0; q < 4; q++) {
            ulonglong2 wa = w2a[q];
            fma2(h2[q * 2], ha, wa.x);
            fma2(h2[q * 2 + 1], ha, wa.y);
            ulonglong2 wb = w2b[q];
            fma2(h2[q * 2], hb, wb.x);
            fma2(h2[q * 2 + 1], hb, wb.y);
        }
    }
    float l = opb3[0];
    #pragma unroll
    for (int jp = 0; jp < 8; jp++) {
        float a, b; unpack2(h2[jp], a, b);
        l = fmaf(fmaxf(a, 0.f), s_w3[2 * jp], l);
        l = fmaf(fmaxf(b, 0.f), s_w3[2 * jp + 1], l);
    }
    l -= (1.f - opmsk[gop]) * 1000.f;
    out[gop] = l;

    // --- per-block online softmax partials ---
    float m = l;
    #pragma unroll
    for (int off = 16; off; off >>= 1)
        m = fmaxf(m, __shfl_xor_sync(0xffffffffu, m, off));
    int wid = tid >> 5, lane = tid & 31;
    if (lane == 0) s_red[wid] = m;
    __syncthreads();
    float bm = s_red[0];
    #pragma unroll
    for (int i = 1; i < 8; i++) bm = fmaxf(bm, s_red[i]);
    float e = __expf(l - bm);
    #pragma unroll
    for (int off = 16; off; off >>= 1)
        e += __shfl_xor_sync(0xffffffffu, e, off);
    if (lane == 0) s_red[8 + wid] = e;
    __syncthreads();
    if (tid == 0) {
        float s = 0.f;
        #pragma unroll
        for (int i = 0; i < 8; i++) s += s_red[8 + i];
        g_bmax[blockIdx.x] = bm;
        g_bsum[blockIdx.x] = s;
    }
}

// ---------------------------------------------------------------------------
// Finalize: every block redundantly reduces the 400 partials (L2-resident),
// then normalizes its 256 logits. (Merged reduce+finalize: one launch less.)
// ---------------------------------------------------------------------------
__global__ __launch_bounds__(256) void finalize_kernel(float* __restrict__ out)
{
    __shared__ float sr[16];
    __shared__ float sM, sS;
    const int tid = threadIdx.x;
    const int wid = tid >> 5, lane = tid & 31;

    float bm0 = g_bmax[tid];
    float bm1 = (tid + 256 < NBLK) ? g_bmax[tid + 256] : -1e30f;
    float m = fmaxf(bm0, bm1);
    #pragma unroll
    for (int off = 16; off; off >>= 1)
        m = fmaxf(m, __shfl_xor_sync(0xffffffffu, m, off));
    if (lane == 0) sr[wid] = m;
    __syncthreads();
    if (tid == 0) {
        float M = sr[0];
        #pragma unroll
        for (int i = 1; i < 8; i++) M = fmaxf(M, sr[i]);
        sM = M;
    }
    __syncthreads();
    const float M = sM;
    float s = g_bsum[tid] * __expf(bm0 - M);
    if (tid + 256 < NBLK) s += g_bsum[tid + 256] * __expf(bm1 - M);
    #pragma unroll
    for (int off = 16; off; off >>= 1)
        s += __shfl_xor_sync(0xffffffffu, s, off);
    if (lane == 0) sr[8 + wid] = s;
    __syncthreads();
    if (tid == 0) {
        float S = 0.f;
        #pragma unroll
        for (int i = 0; i < 8; i++) S += sr[8 + i];
        sS = S;
    }
    __syncthreads();
    const float inv = 1.f / sS;
    const int i = blockIdx.x * 256 + tid;
    out[i] = __expf(out[i] - M) * inv;
}

// ---------------------------------------------------------------------------
// prlvl branch: one block (64 threads) per dag; thread = worker
// ---------------------------------------------------------------------------
__global__ __launch_bounds__(64) void prlvl_kernel(
    const float* __restrict__ prW1,
    const float* __restrict__ prW2, const float* __restrict__ prb2,
    const float* __restrict__ prW3, const float* __restrict__ prb3,
    const float* __restrict__ prmsk,
    float* __restrict__ out)
{
    __shared__ float sA[H1D], sr0[H1D], sw2[H1D * H2D], sb2[H2D], sw3[H2D], sl[NWRK];
    const int d = blockIdx.x;
    const int w = threadIdx.x;
    if (w < H1D) { sA[w] = g_Apr[d * H1D + w]; sr0[w] = prW1[w]; }  // prW1 row 0 = limit weights
    for (int i = w; i < H1D * H2D; i += NWRK) sw2[i] = prW2[i];
    if (w < H2D) { sb2[w] = prb2[w]; sw3[w] = prW3[w]; }
    __syncthreads();

    const float limit = (float)(w + 1);
    float h2[H2D];
    #pragma unroll
    for (int j = 0; j < H2D; j++) h2[j] = sb2[j];
    #pragma unroll
    for (int k = 0; k < H1D; k++) {
        float hv = fmaxf(fmaf(limit, sr0[k], sA[k]), 0.f);
        #pragma unroll
        for (int j = 0; j < H2D; j++) h2[j] = fmaf(hv, sw2[k * H2D + j], h2[j]);
    }
    float l = prb3[0];
    #pragma unroll
    for (int j = 0; j < H2D; j++) l = fmaf(fmaxf(h2[j], 0.f), sw3[j], l);
    l -= (1.f - prmsk[d * NWRK + w]) * 1000.f;
    sl[w] = l;
    __syncthreads();
    float m = -1e30f;
    #pragma unroll 8
    for (int i = 0; i < NWRK; i++) m = fmaxf(m, sl[i]);
    float s = 0.f;
    #pragma unroll 8
    for (int i = 0; i < NWRK; i++) s += __expf(sl[i] - m);
    out[NOPS + d * NWRK + w] = __expf(l - m) / s;
}

// ---------------------------------------------------------------------------
// Launch
// ---------------------------------------------------------------------------
extern "C" void kernel_launch(void* const* d_in, const int* in_sizes, int n_in,
                              void* d_out, int out_size)
{
    const int xi = n_in - 17;
    const float* x     = (const float*)d_in[xi + 0];
    const float* y     = (const float*)d_in[xi + 1];
    const float* z     = (const float*)d_in[xi + 2];
    const float* opmsk = (const float*)d_in[xi + 3];
    const float* prmsk = (const float*)d_in[xi + 4];
    const float* opW1  = (const float*)d_in[xi + 5];
    const float* opb1  = (const float*)d_in[xi + 6];
    const float* opW2  = (const float*)d_in[xi + 7];
    const float* opb2  = (const float*)d_in[xi + 8];
    const float* opW3  = (const float*)d_in[xi + 9];
    const float* opb3  = (const float*)d_in[xi + 10];
    const float* prW1  = (const float*)d_in[xi + 11];
    const float* prb1  = (const float*)d_in[xi + 12];
    const float* prW2  = (const float*)d_in[xi + 13];
    const float* prb2  = (const float*)d_in[xi + 14];
    const float* prW3  = (const float*)d_in[xi + 15];
    const float* prb3  = (const float*)d_in[xi + 16];
    float* out = (float*)d_out;

    static int cfg_done = 0;
    if (!cfg_done) {
        cudaFuncSetAttribute(op_main_kernel,
                             cudaFuncAttributeMaxDynamicSharedMemorySize, SMEM_BYTES);
        cfg_done = 1;
    }

    precompute_kernel<<<NDAG / 4, 128>>>(y, z, opW1, opb1, prW1, prb1);
    op_main_kernel<<<NBLK, 256, SMEM_BYTES>>>(x, opW1, opW2, opb2, opW3, opb3,
                                              opmsk, out);
    finalize_kernel<<<NBLK, 256>>>(out);
    prlvl_kernel<<<NDAG, 64>>>(prW1, prW2, prb2, prW3, prb3, prmsk, out);
}